// round 15
// baseline (speedup 1.0000x reference)
#include <cuda_runtime.h>
#include <cuda_fp16.h>
#include <stdint.h>
#include <math.h>

constexpr int N_ROWS  = 400000;
constexpr int TILE    = 64;
constexpr int THREADS = 512;
constexpr int NT      = N_ROWS / TILE;   // 6250

constexpr int KSTR  = 168;     // big-GEMM fp16 k-stride
constexpr int KV    = 72;      // V-GEMM fp16 k-stride
constexpr int GSTR  = 68;      // gate f32 stride
constexpr int VUSTR = 68;      // v_up f32 stride

// smem byte offsets
constexpr int OFF_W   = 0;                          // 64512: W fp16 [192][168]
constexpr int OFF_A   = OFF_W  + 192 * KSTR * 2;    // 21504: A fp16 [64][168]
constexpr int OFF_BV  = OFF_A  + 64 * KSTR * 2;     // 13824: B_v fp16 [96][72]
constexpr int OFF_AV  = OFF_BV + 96 * KV * 2;       // 27648: Av fp16 [3][64][72]
constexpr int OFF_VUP = OFF_AV + 3 * 64 * KV * 2;   // 52224: v_up f32 [3][64][68]
constexpr int OFF_Z   = OFF_VUP + 3 * 64 * VUSTR * 4; // 13312: z f32 [64][52]
constexpr int OFF_G   = OFF_Z  + 64 * 52 * 4;       // 17408: gate f32 [64][68]
constexpr int OFF_VS  = OFF_G  + 64 * GSTR * 4;     // 3072:  vs f32 [64][12]
constexpr int OFF_BSO = OFF_VS + 64 * 12 * 4;       // 512
constexpr int OFF_BF  = OFF_BSO + 512;              // 256
constexpr int OFF_BDS = OFF_BF + 256;               // 64
constexpr int SMEM_BYTES = OFF_BDS + 64;            // 214400

__device__ __forceinline__ float sigm(float x) { return 1.0f / (1.0f + __expf(-x)); }

__device__ __forceinline__ uint32_t h2(float a, float b) {
    __half2 h; h.x = __float2half(a); h.y = __float2half(b);
    return *reinterpret_cast<uint32_t*>(&h);
}
__device__ __forceinline__ void mma16816(float* c, uint32_t a0, uint32_t a1, uint32_t a2,
                                         uint32_t a3, uint32_t b0, uint32_t b1) {
    asm volatile(
        "mma.sync.aligned.m16n8k16.row.col.f32.f16.f16.f32 "
        "{%0,%1,%2,%3}, {%4,%5,%6,%7}, {%8,%9}, {%0,%1,%2,%3};"
        : "+f"(c[0]), "+f"(c[1]), "+f"(c[2]), "+f"(c[3])
        : "r"(a0), "r"(a1), "r"(a2), "r"(a3), "r"(b0), "r"(b1));
}

// load next tile's inputs into registers (all 512 threads)
__device__ __forceinline__ void ldg_tile(const float* __restrict__ gs,
                                         const float* __restrict__ gv,
                                         const float* __restrict__ gframes,
                                         int row0, int tid,
                                         float* pv, float* ps, float* pf) {
    const int r = tid >> 3, c = tid & 7;
    const float4* vr = (const float4*)(gv + (size_t)(row0 + r) * 192 + c * 24);
    #pragma unroll
    for (int i = 0; i < 6; i++) {
        float4 p = vr[i];
        pv[i * 4 + 0] = p.x; pv[i * 4 + 1] = p.y;
        pv[i * 4 + 2] = p.z; pv[i * 4 + 3] = p.w;
    }
    const float4* sr = (const float4*)(gs + (size_t)(row0 + r) * 128 + c * 16);
    #pragma unroll
    for (int q = 0; q < 4; q++) {
        float4 x = sr[q];
        ps[q * 4 + 0] = x.x; ps[q * 4 + 1] = x.y;
        ps[q * 4 + 2] = x.z; ps[q * 4 + 3] = x.w;
    }
    if (tid < 192) {
        const int fr_ = tid / 3, ff = tid % 3;
        const float* fp = gframes + (size_t)(row0 + fr_) * 9 + ff * 3;
        pf[0] = fp[0]; pf[1] = fp[1]; pf[2] = fp[2];
    }
}
// store prefetched regs into AV (v, fp16, per-f transposed) and A s-slots
__device__ __forceinline__ void sts_av(char* smem, const float* pv, int tid) {
    const int r = tid >> 3, c = tid & 7, k0 = c * 8;
    #pragma unroll
    for (int f = 0; f < 3; f++) {
        uint4 w;
        w.x = h2(pv[0 * 3 + f], pv[1 * 3 + f]);
        w.y = h2(pv[2 * 3 + f], pv[3 * 3 + f]);
        w.z = h2(pv[4 * 3 + f], pv[5 * 3 + f]);
        w.w = h2(pv[6 * 3 + f], pv[7 * 3 + f]);
        *(uint4*)(smem + OFF_AV + f * (64 * KV * 2) + r * (KV * 2) + k0 * 2) = w;
    }
}
__device__ __forceinline__ void sts_a(char* smem, const float* ps, int tid) {
    const int r = tid >> 3, c0 = (tid & 7) * 16;
    char* ah = smem + OFF_A + r * (KSTR * 2) + c0 * 2;
    #pragma unroll
    for (int q = 0; q < 4; q++) {
        *(uint32_t*)(ah + q * 8)     = h2(ps[q * 4 + 0], ps[q * 4 + 1]);
        *(uint32_t*)(ah + q * 8 + 4) = h2(ps[q * 4 + 2], ps[q * 4 + 3]);
    }
}

__global__ void __launch_bounds__(THREADS, 1)
fused_tpp_mma(const float* __restrict__ gs, const float* __restrict__ gv,
              const float* __restrict__ gframes,
              const float* __restrict__ gWd, const float* __restrict__ gWds,
              const float* __restrict__ gbds, const float* __restrict__ gWu,
              const float* __restrict__ gWso, const float* __restrict__ gbso,
              const float* __restrict__ gWg, const float* __restrict__ gbg,
              float* __restrict__ out)
{
    extern __shared__ char smem[];
    float* sZ   = (float*)(smem + OFF_Z);
    float* gate = (float*)(smem + OFF_G);
    float* sVs  = (float*)(smem + OFF_VS);
    float* vup  = (float*)(smem + OFF_VUP);
    float* sbso = (float*)(smem + OFF_BSO);
    float* sbf  = (float*)(smem + OFF_BF);
    float* sbds = (float*)(smem + OFF_BDS);

    const int tid  = threadIdx.x;
    const int wid  = tid >> 5;
    const int lane = tid & 31;
    const int g    = lane >> 2;
    const int t    = lane & 3;

    // ================= one-time staging =================
    if (tid < 128) sbso[tid] = gbso[tid];
    if (tid < 4)   sbds[tid] = (tid < 3) ? gbds[tid] : 0.0f;
    if (tid >= 128 && tid < 192) {
        int n = tid - 128;
        float acc = gbg[n];
        for (int j = 0; j < 128; j++) acc += gbso[j] * gWg[j * 64 + n];
        sbf[n] = acc;
    }
    float* wf = vup;                       // [153][64] f32 scratch
    for (int idx = tid; idx < 153 * 64; idx += THREADS) {
        int k = idx >> 6, n = idx & 63;
        float acc = 0.f;
        #pragma unroll 4
        for (int j = 0; j < 128; j++) acc += gWso[k * 128 + j] * gWg[j * 64 + n];
        wf[idx] = acc;
    }
    __syncthreads();
    for (int i = tid; i < 192 * KSTR; i += THREADS) {
        int n = i / KSTR, k = i % KSTR;
        float w = 0.f;
        if (k < 153) w = (n < 128) ? gWso[k * 128 + n] : wf[k * 64 + (n - 128)];
        *(__half*)(smem + OFF_W + i * 2) = __float2half(w);
    }
    __syncthreads();
    float* wdu = vup;                      // [64 k][64 o] f32 scratch
    for (int idx = tid; idx < 4096; idx += THREADS) {
        int k = idx >> 6, o = idx & 63;
        float acc = 0.f;
        #pragma unroll
        for (int h = 0; h < 16; h++) acc += gWd[k * 16 + h] * gWu[h * 64 + o];
        wdu[idx] = acc;
    }
    __syncthreads();
    for (int i = tid; i < 96 * KV; i += THREADS) {
        int n = i / KV, k = i % KV;
        float w = 0.f;
        if (k < 64) {
            if (n < 64)       w = wdu[k * 64 + n];
            else if (n < 67)  w = gWds[k * 3 + (n - 64)];
            else if (n < 83)  w = gWd[k * 16 + (n - 67)];
        }
        *(__half*)(smem + OFF_BV + i * 2) = __float2half(w);
    }
    __syncthreads();
    for (int i = tid; i < (64 * KSTR * 2) / 4; i += THREADS)
        ((uint32_t*)(smem + OFF_A))[i] = 0;
    for (int i = tid; i < (3 * 64 * KV * 2) / 4; i += THREADS)
        ((uint32_t*)(smem + OFF_AV))[i] = 0;
    __syncthreads();

    float* outS = out;
    float* outV = out + (size_t)N_ROWS * 128;

    float pv[24], ps[16], pf[3];

    // ---- prologue: stage first tile ----
    int tile = blockIdx.x;
    if (tile < NT) {
        ldg_tile(gs, gv, gframes, tile * TILE, tid, pv, ps, pf);
        sts_av(smem, pv, tid);
        sts_a(smem, ps, tid);
    }
    __syncthreads();

    for (; tile < NT; tile += gridDim.x) {
        const int row0 = tile * TILE;
        const int next = tile + gridDim.x;

        // ---- S2: V GEMM [64 x 96 x 64] per f (reads AV, BV) ----
        {
            const int mg = wid & 3, grp = wid >> 2;   // grp 0..3
            #pragma unroll
            for (int i = 0; i < 9; i++) {
                const int u = i * 4 + grp;            // 0..35
                const int f = u / 12, nf = u % 12;
                if (nf == 11) continue;
                float C[4] = {0.f, 0.f, 0.f, 0.f};
                const char* Ar = smem + OFF_AV + f * (64 * KV * 2) + (mg * 16 + g) * (KV * 2) + t * 4;
                const char* Br = smem + OFF_BV + (nf * 8 + g) * (KV * 2) + t * 4;
                #pragma unroll
                for (int ks = 0; ks < 4; ks++) {
                    const int kb = ks * 32;
                    uint32_t a0 = *(const uint32_t*)(Ar + kb);
                    uint32_t a1 = *(const uint32_t*)(Ar + kb + 8 * KV * 2);
                    uint32_t a2 = *(const uint32_t*)(Ar + kb + 16);
                    uint32_t a3 = *(const uint32_t*)(Ar + kb + 8 * KV * 2 + 16);
                    uint32_t b0 = *(const uint32_t*)(Br + kb);
                    uint32_t b1 = *(const uint32_t*)(Br + kb + 16);
                    mma16816(C, a0, a1, a2, a3, b0, b1);
                }
                const int r1 = mg * 16 + g, r2 = r1 + 8;
                const int n0 = nf * 8 + 2 * t;
                if (nf < 8) {
                    float* vb = vup + f * (64 * VUSTR);
                    vb[r1 * VUSTR + n0]     = C[0];
                    vb[r1 * VUSTR + n0 + 1] = C[1];
                    vb[r2 * VUSTR + n0]     = C[2];
                    vb[r2 * VUSTR + n0 + 1] = C[3];
                } else {
                    #pragma unroll
                    for (int e = 0; e < 2; e++) {
                        const int idx = n0 + e - 64;
                        float v1 = C[e], v2 = C[2 + e];
                        if (idx < 3) {
                            float x = v1 + sbds[idx];
                            sVs[r1 * 12 + f * 3 + idx] = x * sigm(x);
                            float y = v2 + sbds[idx];
                            sVs[r2 * 12 + f * 3 + idx] = y * sigm(y);
                        } else if (idx < 19) {
                            const int h = idx - 3;
                            sZ[r1 * 52 + f * 16 + h] = v1;
                            sZ[r2 * 52 + f * 16 + h] = v2;
                        }
                    }
                }
            }
        }
        __syncthreads();

        // ---- S3: norms -> A slots 137..152 ; scalarized -> 128..136 ----
        {
            const int r = tid >> 3, hh = (tid & 7) * 2;
            #pragma unroll
            for (int e = 0; e < 2; e++) {
                const int h = hh + e;
                float z0 = sZ[r * 52 + h];
                float z1 = sZ[r * 52 + 16 + h];
                float z2 = sZ[r * 52 + 32 + h];
                float nr = sqrtf(z0 * z0 + z1 * z1 + z2 * z2);
                *(__half*)(smem + OFF_A + (r * KSTR + 137 + h) * 2) = __float2half(nr);
            }
        }
        if (tid < 192) {
            const int r = tid / 3, f = tid % 3;
            float f0 = pf[0], f1 = pf[1], f2 = pf[2];
            #pragma unroll
            for (int d = 0; d < 3; d++) {
                float val = f0 * sVs[r * 12 + 0 + d] + f1 * sVs[r * 12 + 3 + d] +
                            f2 * sVs[r * 12 + 6 + d];
                *(__half*)(smem + OFF_A + (r * KSTR + 128 + f * 3 + d) * 2) = __float2half(val);
            }
        }
        // issue prefetch for next tile (consumed after S4/S5 barriers)
        if (next < NT)
            ldg_tile(gs, gv, gframes, next * TILE, tid, pv, ps, pf);
        __syncthreads();

        // ---- S4: big GEMM [64 x 192 x 160] fp16 (16 warps: 16m x 48n tiles) ----
        {
            const int mw = (wid & 3) * 16;
            const int nw = (wid >> 2) * 48;
            float C[6][4];
            #pragma unroll
            for (int j = 0; j < 6; j++)
                #pragma unroll
                for (int q = 0; q < 4; q++) C[j][q] = 0.0f;
            const char* Ar = smem + OFF_A + (mw + g) * (KSTR * 2) + t * 4;
            const char* Wr0 = smem + OFF_W + (nw + g) * (KSTR * 2) + t * 4;
            #pragma unroll 2
            for (int ks = 0; ks < 10; ks++) {
                const int kb = ks * 32;
                uint32_t a0 = *(const uint32_t*)(Ar + kb);
                uint32_t a1 = *(const uint32_t*)(Ar + kb + 8 * KSTR * 2);
                uint32_t a2 = *(const uint32_t*)(Ar + kb + 16);
                uint32_t a3 = *(const uint32_t*)(Ar + kb + 8 * KSTR * 2 + 16);
                #pragma unroll
                for (int j = 0; j < 6; j++) {
                    const char* Wr = Wr0 + j * 8 * (KSTR * 2) + kb;
                    uint32_t b0 = *(const uint32_t*)(Wr);
                    uint32_t b1 = *(const uint32_t*)(Wr + 16);
                    mma16816(C[j], a0, a1, a2, a3, b0, b1);
                }
            }
            const int r1 = mw + g, r2 = mw + g + 8;
            #pragma unroll
            for (int j = 0; j < 6; j++) {
                const int n0 = nw + 8 * j + 2 * t;
                if (n0 < 128) {
                    float b0 = sbso[n0], b1 = sbso[n0 + 1];
                    float v0 = C[j][0] + b0, v1 = C[j][1] + b1;
                    float v2 = C[j][2] + b0, v3 = C[j][3] + b1;
                    float2 o1 = {v0 * sigm(v0), v1 * sigm(v1)};
                    float2 o2 = {v2 * sigm(v2), v3 * sigm(v3)};
                    *(float2*)&outS[(size_t)(row0 + r1) * 128 + n0] = o1;
                    *(float2*)&outS[(size_t)(row0 + r2) * 128 + n0] = o2;
                } else {
                    const int c = n0 - 128;
                    float b0 = sbf[c], b1 = sbf[c + 1];
                    gate[r1 * GSTR + c]     = sigm(C[j][0] + b0);
                    gate[r1 * GSTR + c + 1] = sigm(C[j][1] + b1);
                    gate[r2 * GSTR + c]     = sigm(C[j][2] + b0);
                    gate[r2 * GSTR + c + 1] = sigm(C[j][3] + b1);
                }
            }
        }
        __syncthreads();

        // ---- S5: v_out = v_up * gate ; store prefetched regs for next tile ----
        {
            const int r = tid >> 3, o0 = (tid & 7) * 8;
            float gg[8];
            {
                float4 ga = *(const float4*)&gate[r * GSTR + o0];
                float4 gb = *(const float4*)&gate[r * GSTR + o0 + 4];
                gg[0] = ga.x; gg[1] = ga.y; gg[2] = ga.z; gg[3] = ga.w;
                gg[4] = gb.x; gg[5] = gb.y; gg[6] = gb.z; gg[7] = gb.w;
            }
            float vu[3][8];
            #pragma unroll
            for (int f = 0; f < 3; f++) {
                const float* vb = vup + f * (64 * VUSTR) + r * VUSTR + o0;
                float4 va = *(const float4*)(vb);
                float4 vbq = *(const float4*)(vb + 4);
                vu[f][0] = va.x; vu[f][1] = va.y; vu[f][2] = va.z; vu[f][3] = va.w;
                vu[f][4] = vbq.x; vu[f][5] = vbq.y; vu[f][6] = vbq.z; vu[f][7] = vbq.w;
            }
            float vals[24];
            #pragma unroll
            for (int m = 0; m < 8; m++) {
                float gm = gg[m];
                vals[m * 3 + 0] = vu[0][m] * gm;
                vals[m * 3 + 1] = vu[1][m] * gm;
                vals[m * 3 + 2] = vu[2][m] * gm;
            }
            float* ov = outV + (size_t)(row0 + r) * 192 + o0 * 3;
            #pragma unroll
            for (int q = 0; q < 6; q++) {
                float4 w = {vals[q * 4], vals[q * 4 + 1], vals[q * 4 + 2], vals[q * 4 + 3]};
                *(float4*)(ov + q * 4) = w;
            }
        }
        // stage next tile into AV (free since S2 barrier) and A (free since S4 barrier)
        if (next < NT) {
            sts_av(smem, pv, tid);
            sts_a(smem, ps, tid);
        }
        __syncthreads();   // AV/A ready; protects vup/gate/sZ/sVs reuse
    }
}

extern "C" void kernel_launch(void* const* d_in, const int* in_sizes, int n_in,
                              void* d_out, int out_size) {
    const float* s      = (const float*)d_in[0];
    const float* v      = (const float*)d_in[1];
    const float* frames = (const float*)d_in[2];
    const float* Wd     = (const float*)d_in[3];
    const float* Wds    = (const float*)d_in[4];
    const float* bds    = (const float*)d_in[5];
    const float* Wu     = (const float*)d_in[6];
    const float* Wso    = (const float*)d_in[7];
    const float* bso    = (const float*)d_in[8];
    const float* Wg     = (const float*)d_in[9];
    const float* bg     = (const float*)d_in[10];
    float* out          = (float*)d_out;

    int dev = 0;
    cudaGetDevice(&dev);
    int smCount = 148;
    cudaDeviceGetAttribute(&smCount, cudaDevAttrMultiProcessorCount, dev);

    cudaFuncSetAttribute(fused_tpp_mma,
                         cudaFuncAttributeMaxDynamicSharedMemorySize, SMEM_BYTES);
    fused_tpp_mma<<<smCount, THREADS, SMEM_BYTES>>>(s, v, frames, Wd, Wds, bds, Wu,
                                                    Wso, bso, Wg, bg, out);
}

// round 17
// speedup vs baseline: 1.0904x; 1.0904x over previous
#include <cuda_runtime.h>
#include <cuda_fp16.h>
#include <stdint.h>
#include <math.h>

constexpr int N_ROWS  = 400000;
constexpr int TILE    = 64;
constexpr int THREADS = 768;
constexpr int NT      = N_ROWS / TILE;   // 6250

constexpr int KSTR  = 168;     // big-GEMM fp16 k-stride
constexpr int KV    = 72;      // V-GEMM fp16 k-stride (64 + 8 pad); 144B rows
constexpr int GSTR  = 68;      // gate f32 stride
constexpr int VUSTR = 68;      // v_up f32 stride

// smem byte offsets
constexpr int OFF_W   = 0;                          // 64512: W fp16 [192][168]
constexpr int OFF_A   = OFF_W  + 192 * KSTR * 2;    // 21504: A fp16 [64][168]
constexpr int OFF_BV  = OFF_A  + 64 * KSTR * 2;     // 13824: B_v fp16 [96][72]
constexpr int OFF_AV  = OFF_BV + 96 * KV * 2;       // 27648: Av fp16 [3][64][72]
constexpr int OFF_VUP = OFF_AV + 3 * 64 * KV * 2;   // 52224: v_up f32 [3][64][68] (+init scratch)
constexpr int OFF_Z   = OFF_VUP + 3 * 64 * VUSTR * 4; // 13312: z f32 [64][52]
constexpr int OFF_G   = OFF_Z  + 64 * 52 * 4;       // 17408: gate f32 [64][68]
constexpr int OFF_VS  = OFF_G  + 64 * GSTR * 4;     // 3072:  vs f32 [64][12]
constexpr int OFF_BSO = OFF_VS + 64 * 12 * 4;       // 512
constexpr int OFF_BF  = OFF_BSO + 512;              // 256
constexpr int OFF_BDS = OFF_BF + 256;               // 64
constexpr int SMEM_BYTES = OFF_BDS + 64;            // 214400

// sigmoid via single-MUFU hardware tanh:  sigm(x) = 0.5*tanh(0.5x) + 0.5
__device__ __forceinline__ float sigm(float x) {
    float th;
    asm("tanh.approx.f32 %0, %1;" : "=f"(th) : "f"(x * 0.5f));
    return fmaf(th, 0.5f, 0.5f);
}

__device__ __forceinline__ uint32_t h2(float a, float b) {
    __half2 h; h.x = __float2half(a); h.y = __float2half(b);
    return *reinterpret_cast<uint32_t*>(&h);
}
__device__ __forceinline__ void mma16816(float* c, uint32_t a0, uint32_t a1, uint32_t a2,
                                         uint32_t a3, uint32_t b0, uint32_t b1) {
    asm volatile(
        "mma.sync.aligned.m16n8k16.row.col.f32.f16.f16.f32 "
        "{%0,%1,%2,%3}, {%4,%5,%6,%7}, {%8,%9}, {%0,%1,%2,%3};"
        : "+f"(c[0]), "+f"(c[1]), "+f"(c[2]), "+f"(c[3])
        : "r"(a0), "r"(a1), "r"(a2), "r"(a3), "r"(b0), "r"(b1));
}

__global__ void __launch_bounds__(THREADS, 1)
fused_tpp_mma(const float* __restrict__ gs, const float* __restrict__ gv,
              const float* __restrict__ gframes,
              const float* __restrict__ gWd, const float* __restrict__ gWds,
              const float* __restrict__ gbds, const float* __restrict__ gWu,
              const float* __restrict__ gWso, const float* __restrict__ gbso,
              const float* __restrict__ gWg, const float* __restrict__ gbg,
              float* __restrict__ out)
{
    extern __shared__ char smem[];
    float* sZ   = (float*)(smem + OFF_Z);
    float* gate = (float*)(smem + OFF_G);
    float* sVs  = (float*)(smem + OFF_VS);
    float* vup  = (float*)(smem + OFF_VUP);
    float* sbso = (float*)(smem + OFF_BSO);
    float* sbf  = (float*)(smem + OFF_BF);
    float* sbds = (float*)(smem + OFF_BDS);

    const int tid  = threadIdx.x;
    const int wid  = tid >> 5;
    const int lane = tid & 31;
    const int g    = lane >> 2;           // fragment group 0..7
    const int t    = lane & 3;            // thread-in-group

    // ================= one-time staging =================
    if (tid < 128) sbso[tid] = gbso[tid];
    if (tid < 4)   sbds[tid] = (tid < 3) ? gbds[tid] : 0.0f;
    if (tid >= 128 && tid < 192) {
        int n = tid - 128;
        float acc = gbg[n];
        for (int j = 0; j < 128; j++) acc += gbso[j] * gWg[j * 64 + n];
        sbf[n] = acc;
    }
    // (1) fused gate weight Wf[k][n] -> scratch in VUP region
    float* wf = vup;                       // [153][64] f32
    for (int idx = tid; idx < 153 * 64; idx += THREADS) {
        int k = idx >> 6, n = idx & 63;
        float acc = 0.f;
        #pragma unroll 4
        for (int j = 0; j < 128; j++) acc += gWso[k * 128 + j] * gWg[j * 64 + n];
        wf[idx] = acc;
    }
    __syncthreads();
    // (2) W big fp16 [192 n][KSTR k]
    for (int i = tid; i < 192 * KSTR; i += THREADS) {
        int n = i / KSTR, k = i % KSTR;
        float w = 0.f;
        if (k < 153) w = (n < 128) ? gWso[k * 128 + n] : wf[k * 64 + (n - 128)];
        *(__half*)(smem + OFF_W + i * 2) = __float2half(w);
    }
    __syncthreads();
    // (3) Wdu = W_down @ W_up -> scratch (overwrites wf; W big already built)
    float* wdu = vup;                      // [64 k][64 o] f32
    for (int idx = tid; idx < 4096; idx += THREADS) {
        int k = idx >> 6, o = idx & 63;
        float acc = 0.f;
        #pragma unroll
        for (int h = 0; h < 16; h++) acc += gWd[k * 16 + h] * gWu[h * 64 + o];
        wdu[idx] = acc;
    }
    __syncthreads();
    // (4) B_v fp16 [96 n][KV k]: n<64 = Wdu col n; 64..66 = Wds col; 67..82 = Wd col; rest 0
    for (int i = tid; i < 96 * KV; i += THREADS) {
        int n = i / KV, k = i % KV;
        float w = 0.f;
        if (k < 64) {
            if (n < 64)       w = wdu[k * 64 + n];
            else if (n < 67)  w = gWds[k * 3 + (n - 64)];
            else if (n < 83)  w = gWd[k * 16 + (n - 67)];
        }
        *(__half*)(smem + OFF_BV + i * 2) = __float2half(w);
    }
    __syncthreads();
    // (5) zero A big + Av (pads stay zero forever)
    for (int i = tid; i < (64 * KSTR * 2) / 4; i += THREADS)
        ((uint32_t*)(smem + OFF_A))[i] = 0;
    for (int i = tid; i < (3 * 64 * KV * 2) / 4; i += THREADS)
        ((uint32_t*)(smem + OFF_AV))[i] = 0;
    __syncthreads();

    float* outS = out;
    float* outV = out + (size_t)N_ROWS * 128;

    for (int tile = blockIdx.x; tile < NT; tile += gridDim.x) {
        const int row0 = tile * TILE;

        // ---- S1: stage Av (v slices, fp16) + s -> A big ----
        if (tid < 512) {
            const int r = tid >> 3, c = tid & 7, k0 = c * 8;
            const float4* vr = (const float4*)(gv + (size_t)(row0 + r) * 192 + k0 * 3);
            float vals[24];
            #pragma unroll
            for (int i = 0; i < 6; i++) {
                float4 p = vr[i];
                vals[i * 4 + 0] = p.x; vals[i * 4 + 1] = p.y;
                vals[i * 4 + 2] = p.z; vals[i * 4 + 3] = p.w;
            }
            #pragma unroll
            for (int f = 0; f < 3; f++) {
                uint4 w;
                w.x = h2(vals[0 * 3 + f], vals[1 * 3 + f]);
                w.y = h2(vals[2 * 3 + f], vals[3 * 3 + f]);
                w.z = h2(vals[4 * 3 + f], vals[5 * 3 + f]);
                w.w = h2(vals[6 * 3 + f], vals[7 * 3 + f]);
                *(uint4*)(smem + OFF_AV + f * (64 * KV * 2) + r * (KV * 2) + k0 * 2) = w;
            }
        } else {
            #pragma unroll
            for (int i = 0; i < 2; i++) {
                const int u = (tid - 512) * 2 + i;
                const int rr = u >> 3, c0 = (u & 7) * 16;
                const float4* sr = (const float4*)(gs + (size_t)(row0 + rr) * 128 + c0);
                char* ah = smem + OFF_A + rr * (KSTR * 2) + c0 * 2;
                #pragma unroll
                for (int q = 0; q < 4; q++) {
                    float4 x = sr[q];
                    *(uint32_t*)(ah + q * 8)     = h2(x.x, x.y);
                    *(uint32_t*)(ah + q * 8 + 4) = h2(x.z, x.w);
                }
            }
        }
        __syncthreads();

        // ---- S2: V GEMM [64 x 96 x 64] per f via shared B; scatter epilogue ----
        {
            const int mg = wid & 3, grp = wid >> 2;
            #pragma unroll
            for (int i = 0; i < 6; i++) {
                const int u = grp * 6 + i;
                const int f = u / 12, nf = u % 12;
                if (nf == 11) continue;
                float C[4] = {0.f, 0.f, 0.f, 0.f};
                const char* Ar = smem + OFF_AV + f * (64 * KV * 2) + (mg * 16 + g) * (KV * 2) + t * 4;
                const char* Br = smem + OFF_BV + (nf * 8 + g) * (KV * 2) + t * 4;
                #pragma unroll
                for (int ks = 0; ks < 4; ks++) {
                    const int kb = ks * 32;
                    uint32_t a0 = *(const uint32_t*)(Ar + kb);
                    uint32_t a1 = *(const uint32_t*)(Ar + kb + 8 * KV * 2);
                    uint32_t a2 = *(const uint32_t*)(Ar + kb + 16);
                    uint32_t a3 = *(const uint32_t*)(Ar + kb + 8 * KV * 2 + 16);
                    uint32_t b0 = *(const uint32_t*)(Br + kb);
                    uint32_t b1 = *(const uint32_t*)(Br + kb + 16);
                    mma16816(C, a0, a1, a2, a3, b0, b1);
                }
                const int r1 = mg * 16 + g, r2 = r1 + 8;
                const int n0 = nf * 8 + 2 * t;
                if (nf < 8) {
                    float* vb = vup + f * (64 * VUSTR);
                    vb[r1 * VUSTR + n0]     = C[0];
                    vb[r1 * VUSTR + n0 + 1] = C[1];
                    vb[r2 * VUSTR + n0]     = C[2];
                    vb[r2 * VUSTR + n0 + 1] = C[3];
                } else {
                    #pragma unroll
                    for (int e = 0; e < 2; e++) {
                        const int idx = n0 + e - 64;
                        float v1 = C[e], v2 = C[2 + e];
                        if (idx < 3) {
                            float x = v1 + sbds[idx];
                            sVs[r1 * 12 + f * 3 + idx] = x * sigm(x);
                            float y = v2 + sbds[idx];
                            sVs[r2 * 12 + f * 3 + idx] = y * sigm(y);
                        } else if (idx < 19) {
                            const int h = idx - 3;
                            sZ[r1 * 52 + f * 16 + h] = v1;
                            sZ[r2 * 52 + f * 16 + h] = v2;
                        }
                    }
                }
            }
        }
        __syncthreads();

        // ---- S3: norms -> A slots 137..152 ; scalarized -> 128..136 ----
        if (tid < 512) {
            const int r = tid >> 3, hh = (tid & 7) * 2;
            #pragma unroll
            for (int e = 0; e < 2; e++) {
                const int h = hh + e;
                float z0 = sZ[r * 52 + h];
                float z1 = sZ[r * 52 + 16 + h];
                float z2 = sZ[r * 52 + 32 + h];
                float nr = sqrtf(z0 * z0 + z1 * z1 + z2 * z2);
                *(__half*)(smem + OFF_A + (r * KSTR + 137 + h) * 2) = __float2half(nr);
            }
        } else if (tid < 512 + 192) {
            const int u = tid - 512;
            const int r = u / 3, f = u % 3;
            const float* fr = gframes + (size_t)(row0 + r) * 9 + f * 3;
            float f0 = fr[0], f1 = fr[1], f2 = fr[2];
            #pragma unroll
            for (int d = 0; d < 3; d++) {
                float val = f0 * sVs[r * 12 + 0 + d] + f1 * sVs[r * 12 + 3 + d] +
                            f2 * sVs[r * 12 + 6 + d];
                *(__half*)(smem + OFF_A + (r * KSTR + 128 + f * 3 + d) * 2) = __float2half(val);
            }
        }
        __syncthreads();

        // ---- S4: big GEMM [64 x 192 x 160] fp16, single pass ----
        {
            const int mw = (wid & 3) * 16;
            const int nw = (wid >> 2) * 32;
            float C[4][4];
            #pragma unroll
            for (int j = 0; j < 4; j++)
                #pragma unroll
                for (int q = 0; q < 4; q++) C[j][q] = 0.0f;
            const char* Ar = smem + OFF_A + (mw + g) * (KSTR * 2) + t * 4;
            const char* Wr0 = smem + OFF_W + (nw + g) * (KSTR * 2) + t * 4;
            #pragma unroll 2
            for (int ks = 0; ks < 10; ks++) {
                const int kb = ks * 32;
                uint32_t a0 = *(const uint32_t*)(Ar + kb);
                uint32_t a1 = *(const uint32_t*)(Ar + kb + 8 * KSTR * 2);
                uint32_t a2 = *(const uint32_t*)(Ar + kb + 16);
                uint32_t a3 = *(const uint32_t*)(Ar + kb + 8 * KSTR * 2 + 16);
                #pragma unroll
                for (int j = 0; j < 4; j++) {
                    const char* Wr = Wr0 + j * 8 * (KSTR * 2) + kb;
                    uint32_t b0 = *(const uint32_t*)(Wr);
                    uint32_t b1 = *(const uint32_t*)(Wr + 16);
                    mma16816(C[j], a0, a1, a2, a3, b0, b1);
                }
            }
            // epilogue: bias + silu -> gmem (n<128); sigmoid -> gate smem
            const int r1 = mw + g, r2 = mw + g + 8;
            #pragma unroll
            for (int j = 0; j < 4; j++) {
                const int n0 = nw + 8 * j + 2 * t;
                if (n0 < 128) {
                    float b0 = sbso[n0], b1 = sbso[n0 + 1];
                    float v0 = C[j][0] + b0, v1 = C[j][1] + b1;
                    float v2 = C[j][2] + b0, v3 = C[j][3] + b1;
                    float2 o1 = {v0 * sigm(v0), v1 * sigm(v1)};
                    float2 o2 = {v2 * sigm(v2), v3 * sigm(v3)};
                    *(float2*)&outS[(size_t)(row0 + r1) * 128 + n0] = o1;
                    *(float2*)&outS[(size_t)(row0 + r2) * 128 + n0] = o2;
                } else {
                    const int c = n0 - 128;
                    float b0 = sbf[c], b1 = sbf[c + 1];
                    gate[r1 * GSTR + c]     = sigm(C[j][0] + b0);
                    gate[r1 * GSTR + c + 1] = sigm(C[j][1] + b1);
                    gate[r2 * GSTR + c]     = sigm(C[j][2] + b0);
                    gate[r2 * GSTR + c + 1] = sigm(C[j][3] + b1);
                }
            }
        }
        __syncthreads();

        // ---- S5: v_out[r][o][f] = v_up[f][r][o] * gate[r][o] ----
        if (tid < 512) {
            const int r = tid >> 3, o0 = (tid & 7) * 8;
            float gg[8];
            {
                float4 ga = *(const float4*)&gate[r * GSTR + o0];
                float4 gb = *(const float4*)&gate[r * GSTR + o0 + 4];
                gg[0] = ga.x; gg[1] = ga.y; gg[2] = ga.z; gg[3] = ga.w;
                gg[4] = gb.x; gg[5] = gb.y; gg[6] = gb.z; gg[7] = gb.w;
            }
            float vu[3][8];
            #pragma unroll
            for (int f = 0; f < 3; f++) {
                const float* vb = vup + f * (64 * VUSTR) + r * VUSTR + o0;
                float4 va = *(const float4*)(vb);
                float4 vbq = *(const float4*)(vb + 4);
                vu[f][0] = va.x; vu[f][1] = va.y; vu[f][2] = va.z; vu[f][3] = va.w;
                vu[f][4] = vbq.x; vu[f][5] = vbq.y; vu[f][6] = vbq.z; vu[f][7] = vbq.w;
            }
            float vals[24];
            #pragma unroll
            for (int m = 0; m < 8; m++) {
                float gm = gg[m];
                vals[m * 3 + 0] = vu[0][m] * gm;
                vals[m * 3 + 1] = vu[1][m] * gm;
                vals[m * 3 + 2] = vu[2][m] * gm;
            }
            float* ov = outV + (size_t)(row0 + r) * 192 + o0 * 3;
            #pragma unroll
            for (int q = 0; q < 6; q++) {
                float4 w = {vals[q * 4], vals[q * 4 + 1], vals[q * 4 + 2], vals[q * 4 + 3]};
                *(float4*)(ov + q * 4) = w;
            }
        }
        __syncthreads();   // protect vup/gate/sZ/sVs/A before next tile
    }
}

extern "C" void kernel_launch(void* const* d_in, const int* in_sizes, int n_in,
                              void* d_out, int out_size) {
    const float* s      = (const float*)d_in[0];
    const float* v      = (const float*)d_in[1];
    const float* frames = (const float*)d_in[2];
    const float* Wd     = (const float*)d_in[3];
    const float* Wds    = (const float*)d_in[4];
    const float* bds    = (const float*)d_in[5];
    const float* Wu     = (const float*)d_in[6];
    const float* Wso    = (const float*)d_in[7];
    const float* bso    = (const float*)d_in[8];
    const float* Wg     = (const float*)d_in[9];
    const float* bg     = (const float*)d_in[10];
    float* out          = (float*)d_out;

    int dev = 0;
    cudaGetDevice(&dev);
    int smCount = 148;
    cudaDeviceGetAttribute(&smCount, cudaDevAttrMultiProcessorCount, dev);

    cudaFuncSetAttribute(fused_tpp_mma,
                         cudaFuncAttributeMaxDynamicSharedMemorySize, SMEM_BYTES);
    fused_tpp_mma<<<smCount, THREADS, SMEM_BYTES>>>(s, v, frames, Wd, Wds, bds, Wu,
                                                    Wso, bso, Wg, bg, out);
}